// round 2
// baseline (speedup 1.0000x reference)
#include <cuda_runtime.h>

#define HW 2304           // 48*48
#define NIMG 128          // B*N = 16*8
#define PRED_I_ELEMS 884736   // 16*8*3*48*48
#define PRED_ELEMS   110592   // 16*3*48*48

// Fallback scratch if out buffer only holds pred_img (kept unused otherwise).
__device__ float g_pred_i_scratch[PRED_I_ELEMS];

// One block per (b,n) image. 384 threads = 8 rows of 48; 6 row-iterations cover 48 rows.
__global__ __launch_bounds__(384, 2)
void conv_fused_kernel(const float* __restrict__ frames,
                       const float* __restrict__ core,
                       const float* __restrict__ kwt,
                       float* __restrict__ out_pred_i) {
    const int bn = blockIdx.x;

    // --- channel-summed, zero-padded frames tile: fsum[(y+2)*52 + (x+2)] ---
    __shared__ float fsum[52 * 52];
    {
        const float* fr = frames + (size_t)bn * 3 * HW;
        for (int i = threadIdx.x; i < 52 * 52; i += 384) {
            int yy = i / 52 - 2;
            int xx = i % 52 - 2;
            float v = 0.f;
            if ((unsigned)yy < 48u && (unsigned)xx < 48u) {
                int p = yy * 48 + xx;
                v = fr[p] + fr[HW + p] + fr[2 * HW + p];
            }
            fsum[i] = v;
        }
    }
    __syncthreads();

    const float* cb = core + (size_t)bn * 300 * HW;  // [300, H, W] planes
    const float* kb = kwt  + (size_t)bn * 12  * HW;  // [4, 3, H, W] planes
    float*       ob = out_pred_i + (size_t)bn * 3 * HW;

    const int x  = threadIdx.x % 48;
    const int y0 = threadIdx.x / 48;

    #pragma unroll 1
    for (int it = 0; it < 6; ++it) {
        const int y   = y0 + it * 8;
        const int pix = y * 48 + x;

        // 25 shifted frame-sums: shift (i,j) -> fsum[(y+i)*52 + (x+j)]
        float fs[25];
        #pragma unroll
        for (int i = 0; i < 5; ++i)
            #pragma unroll
            for (int j = 0; j < 5; ++j)
                fs[i * 5 + j] = fsum[(y + i) * 52 + (x + j)];

        float a0 = 0.f, a1 = 0.f, a2 = 0.f;
        #pragma unroll
        for (int g = 0; g < 4; ++g) {
            // pk[g,k,c] == core flat mid-index m = g*75 + k*3 + c
            const float* cg = cb + (size_t)(g * 75) * HW + pix;
            float s0 = 0.f, s1 = 0.f, s2 = 0.f;
            #pragma unroll
            for (int k = 0; k < 25; ++k) {
                const float f = fs[k];
                s0 = fmaf(f, cg[(size_t)(3 * k + 0) * HW], s0);
                s1 = fmaf(f, cg[(size_t)(3 * k + 1) * HW], s1);
                s2 = fmaf(f, cg[(size_t)(3 * k + 2) * HW], s2);
            }
            a0 = fmaf(kb[(g * 3 + 0) * HW + pix], s0, a0);
            a1 = fmaf(kb[(g * 3 + 1) * HW + pix], s1, a1);
            a2 = fmaf(kb[(g * 3 + 2) * HW + pix], s2, a2);
        }
        ob[pix]          = 0.25f * a0;   // mean over the 4 kernel groups
        ob[HW + pix]     = 0.25f * a1;
        ob[2 * HW + pix] = 0.25f * a2;
    }
}

// pred_img[b,c,y,x] = mean_n pred_img_i[b,n,c,y,x]
__global__ __launch_bounds__(256)
void mean_over_n_kernel(const float* __restrict__ pred_i,
                        float* __restrict__ pred) {
    int idx = blockIdx.x * blockDim.x + threadIdx.x;
    if (idx >= PRED_ELEMS) return;
    int b = idx / (3 * HW);
    int r = idx - b * 3 * HW;
    const float* p = pred_i + (size_t)b * 8 * 3 * HW + r;
    float s = 0.f;
    #pragma unroll
    for (int n = 0; n < 8; ++n)
        s += p[(size_t)n * 3 * HW];
    pred[idx] = 0.125f * s;
}

extern "C" void kernel_launch(void* const* d_in, const int* in_sizes, int n_in,
                              void* d_out, int out_size) {
    const float* frames = (const float*)d_in[0];
    const float* core   = (const float*)d_in[1];
    const float* kwt    = (const float*)d_in[2];
    float* out = (float*)d_out;

    const int mean_blocks = (PRED_ELEMS + 255) / 256;

    if (out_size >= PRED_I_ELEMS + PRED_ELEMS) {
        // [pred_img_i | pred_img] concatenated
        conv_fused_kernel<<<NIMG, 384>>>(frames, core, kwt, out);
        mean_over_n_kernel<<<mean_blocks, 256>>>(out, out + PRED_I_ELEMS);
    } else if (out_size >= PRED_I_ELEMS) {
        conv_fused_kernel<<<NIMG, 384>>>(frames, core, kwt, out);
    } else {
        // Only pred_img requested: stage pred_img_i in device-global scratch.
        conv_fused_kernel<<<NIMG, 384>>>(frames, core, kwt, g_pred_i_scratch);
        mean_over_n_kernel<<<mean_blocks, 256>>>(g_pred_i_scratch, out);
    }
}

// round 4
// speedup vs baseline: 1.1246x; 1.1246x over previous
#include <cuda_runtime.h>

#define HW 2304               // 48*48
#define HW4 576               // HW / 4 (float4 plane stride)
#define NIMG 128              // B*N
#define PRED_I_ELEMS 884736   // 16*8*3*48*48
#define PRED_ELEMS   110592   // 16*3*48*48

__device__ float g_pred_i_scratch[PRED_I_ELEMS];

__device__ __forceinline__ void fma4(float4& a, float s, const float4 b) {
    a.x = fmaf(s, b.x, a.x); a.y = fmaf(s, b.y, a.y);
    a.z = fmaf(s, b.z, a.z); a.w = fmaf(s, b.w, a.w);
}

// One block per (b,n). 288 threads; each thread owns a 4-pixel quad,
// 2 row-iterations (rows 0-23 then 24-47). All core/kwt/out accesses are LDG.128.
__global__ __launch_bounds__(288, 1)
void conv_fused_kernel(const float* __restrict__ frames,
                       const float* __restrict__ core,
                       const float* __restrict__ kwt,
                       float* __restrict__ out_pred_i) {
    const int bn = blockIdx.x;

    // channel-summed, zero-padded frame tile: fsum[(y+2)*52 + (x+2)]
    __shared__ float fsum[52 * 52];
    {
        const float* fr = frames + (size_t)bn * 3 * HW;
        for (int i = threadIdx.x; i < 52 * 52; i += 288) {
            int yy = i / 52 - 2;
            int xx = i % 52 - 2;
            float v = 0.f;
            if ((unsigned)yy < 48u && (unsigned)xx < 48u) {
                int p = yy * 48 + xx;
                v = fr[p] + fr[HW + p] + fr[2 * HW + p];
            }
            fsum[i] = v;
        }
    }
    __syncthreads();

    const float* cb = core + (size_t)bn * 300 * HW;  // [300,H,W] planes
    const float* kb = kwt  + (size_t)bn * 12  * HW;  // [4,3,H,W] planes
    float*       ob = out_pred_i + (size_t)bn * 3 * HW;

    const int x4 = threadIdx.x % 12;      // quad index in row
    const int y0 = threadIdx.x / 12;      // 0..23
    const int xb = x4 * 4;

    #pragma unroll 1
    for (int it = 0; it < 2; ++it) {
        const int y    = y0 + it * 24;
        const int pixq = y * 48 + xb;     // float index of quad start (16B aligned)

        // 5x8 window of shifted frame-sums covering the 4 pixels' 5x5 taps
        float win[5][8];
        #pragma unroll
        for (int i = 0; i < 5; ++i)
            #pragma unroll
            for (int j = 0; j < 8; ++j)
                win[i][j] = fsum[(y + i) * 52 + xb + j];

        float4 a0 = {0,0,0,0}, a1 = {0,0,0,0}, a2 = {0,0,0,0};

        #pragma unroll
        for (int g = 0; g < 4; ++g) {
            // pk[g,k,c] lives at core mid-index m = g*75 + 3k + c
            const float4* cg = (const float4*)(cb + (size_t)(g * 75) * HW + pixq);
            float4 s0 = {0,0,0,0}, s1 = {0,0,0,0}, s2 = {0,0,0,0};
            #pragma unroll
            for (int k = 0; k < 25; ++k) {
                const int i = k / 5, j = k % 5;
                const float4 c0 = cg[(3 * k + 0) * HW4];
                const float4 c1 = cg[(3 * k + 1) * HW4];
                const float4 c2 = cg[(3 * k + 2) * HW4];
                // per-lane shifted frame sums
                s0.x = fmaf(win[i][j+0], c0.x, s0.x);
                s0.y = fmaf(win[i][j+1], c0.y, s0.y);
                s0.z = fmaf(win[i][j+2], c0.z, s0.z);
                s0.w = fmaf(win[i][j+3], c0.w, s0.w);
                s1.x = fmaf(win[i][j+0], c1.x, s1.x);
                s1.y = fmaf(win[i][j+1], c1.y, s1.y);
                s1.z = fmaf(win[i][j+2], c1.z, s1.z);
                s1.w = fmaf(win[i][j+3], c1.w, s1.w);
                s2.x = fmaf(win[i][j+0], c2.x, s2.x);
                s2.y = fmaf(win[i][j+1], c2.y, s2.y);
                s2.z = fmaf(win[i][j+2], c2.z, s2.z);
                s2.w = fmaf(win[i][j+3], c2.w, s2.w);
            }
            const float4* kg = (const float4*)(kb + pixq);
            const float4 w0 = kg[(g * 3 + 0) * HW4];
            const float4 w1 = kg[(g * 3 + 1) * HW4];
            const float4 w2 = kg[(g * 3 + 2) * HW4];
            a0.x = fmaf(w0.x, s0.x, a0.x); a0.y = fmaf(w0.y, s0.y, a0.y);
            a0.z = fmaf(w0.z, s0.z, a0.z); a0.w = fmaf(w0.w, s0.w, a0.w);
            a1.x = fmaf(w1.x, s1.x, a1.x); a1.y = fmaf(w1.y, s1.y, a1.y);
            a1.z = fmaf(w1.z, s1.z, a1.z); a1.w = fmaf(w1.w, s1.w, a1.w);
            a2.x = fmaf(w2.x, s2.x, a2.x); a2.y = fmaf(w2.y, s2.y, a2.y);
            a2.z = fmaf(w2.z, s2.z, a2.z); a2.w = fmaf(w2.w, s2.w, a2.w);
        }

        float4* o4 = (float4*)(ob + pixq);
        const float4 q = {0.25f, 0.25f, 0.25f, 0.25f};
        float4 r0 = {q.x*a0.x, q.y*a0.y, q.z*a0.z, q.w*a0.w};
        float4 r1 = {q.x*a1.x, q.y*a1.y, q.z*a1.z, q.w*a1.w};
        float4 r2 = {q.x*a2.x, q.y*a2.y, q.z*a2.z, q.w*a2.w};
        o4[0]       = r0;
        o4[HW4]     = r1;
        o4[2 * HW4] = r2;
    }
}

// pred_img = mean over n of pred_img_i, float4-vectorized.
__global__ __launch_bounds__(256)
void mean_over_n_kernel(const float* __restrict__ pred_i,
                        float* __restrict__ pred) {
    const int nq = PRED_ELEMS / 4;            // 27648 quads
    int idx = blockIdx.x * blockDim.x + threadIdx.x;
    if (idx >= nq) return;
    const int perb = 3 * HW4;                 // 1728 quads per (b, c, h, w) slab
    int b = idx / perb;
    int r = idx - b * perb;
    const float4* p = (const float4*)pred_i + (size_t)b * 8 * perb + r;
    float4 s = {0,0,0,0};
    #pragma unroll
    for (int n = 0; n < 8; ++n) {
        float4 v = p[(size_t)n * perb];
        s.x += v.x; s.y += v.y; s.z += v.z; s.w += v.w;
    }
    s.x *= 0.125f; s.y *= 0.125f; s.z *= 0.125f; s.w *= 0.125f;
    ((float4*)pred)[idx] = s;
}

extern "C" void kernel_launch(void* const* d_in, const int* in_sizes, int n_in,
                              void* d_out, int out_size) {
    const float* frames = (const float*)d_in[0];
    const float* core   = (const float*)d_in[1];
    const float* kwt    = (const float*)d_in[2];
    float* out = (float*)d_out;

    const int mean_blocks = (PRED_ELEMS / 4 + 255) / 256;

    if (out_size >= PRED_I_ELEMS + PRED_ELEMS) {
        conv_fused_kernel<<<NIMG, 288>>>(frames, core, kwt, out);
        mean_over_n_kernel<<<mean_blocks, 256>>>(out, out + PRED_I_ELEMS);
    } else if (out_size >= PRED_I_ELEMS) {
        conv_fused_kernel<<<NIMG, 288>>>(frames, core, kwt, out);
    } else {
        conv_fused_kernel<<<NIMG, 288>>>(frames, core, kwt, g_pred_i_scratch);
        mean_over_n_kernel<<<mean_blocks, 256>>>(g_pred_i_scratch, out);
    }
}